// round 9
// baseline (speedup 1.0000x reference)
#include <cuda_runtime.h>
#include <cuda_bf16.h>
#include <cstdint>
#include <cstddef>
#include <mma.h>

using namespace nvcuda;

#define B_    8192
#define NNEG  8192
#define D_    1024

#define BM 128
#define BN 256
#define BK 64
#define LDA 72                 // BK + 8 bf16 pad -> 144B row stride
#define NIT    (D_ / BK)       // 16
#define NTILES (NNEG / BN)     // 32

#define A_STAGE (BM * LDA)                 // bf16 elems: 9216  (18432 B)
#define B_STAGE (BN * LDA)                 // bf16 elems: 18432 (36864 B)
#define STAGE_ELEMS (A_STAGE + B_STAGE)    // 27648 elems = 55296 B
#define PIPE_BYTES (2 * STAGE_ELEMS * 2)   // 110592
#define EPI_LD 260
#define EPI_BYTES (BM * EPI_LD * 4)        // 133120
#define SMEM_BYTES (EPI_BYTES > PIPE_BYTES ? EPI_BYTES : PIPE_BYTES)

__device__ __align__(16) __nv_bfloat16 g_Qh[(size_t)B_ * D_];
__device__ __align__(16) __nv_bfloat16 g_Nh[(size_t)NNEG * D_];
__device__ float g_pos[B_];
__device__ float g_part[(size_t)B_ * NTILES];
__device__ float g_row[B_];

__constant__ float c_invT = 1.0f / 0.92f;

// ---------------------------------------------------------------------------
// Kernel 1: per-row ||q||, ||p||, q.p -> pos_sim, normalized bf16 Q
// ---------------------------------------------------------------------------
__global__ void k_norm_qp(const float* __restrict__ q, const float* __restrict__ p) {
    int b = blockIdx.x, t = threadIdx.x;
    float4 a = reinterpret_cast<const float4*>(q + (size_t)b * D_)[t];
    float4 c = reinterpret_cast<const float4*>(p + (size_t)b * D_)[t];

    float qq = a.x*a.x + a.y*a.y + a.z*a.z + a.w*a.w;
    float pp = c.x*c.x + c.y*c.y + c.z*c.z + c.w*c.w;
    float qp = a.x*c.x + a.y*c.y + a.z*c.z + a.w*c.w;
    #pragma unroll
    for (int o = 16; o > 0; o >>= 1) {
        qq += __shfl_xor_sync(0xffffffffu, qq, o);
        pp += __shfl_xor_sync(0xffffffffu, pp, o);
        qp += __shfl_xor_sync(0xffffffffu, qp, o);
    }
    __shared__ float sq[8], sp[8], sc[8];
    __shared__ float s_inv;
    int w = t >> 5, l = t & 31;
    if (l == 0) { sq[w] = qq; sp[w] = pp; sc[w] = qp; }
    __syncthreads();
    if (t == 0) {
        float QQ = 0.f, PP = 0.f, QP = 0.f;
        #pragma unroll
        for (int i = 0; i < 8; i++) { QQ += sq[i]; PP += sp[i]; QP += sc[i]; }
        float qn = sqrtf(QQ), pn = sqrtf(PP);
        g_pos[b] = QP / fmaxf(qn * pn, 1e-6f);
        s_inv = (qn > 0.f) ? (1.0f / qn) : 0.f;
    }
    __syncthreads();
    float inv = s_inv;
    __nv_bfloat162 lo = __floats2bfloat162_rn(a.x * inv, a.y * inv);
    __nv_bfloat162 hi = __floats2bfloat162_rn(a.z * inv, a.w * inv);
    __nv_bfloat162* dst = reinterpret_cast<__nv_bfloat162*>(g_Qh) + (size_t)b * (D_ / 2) + t * 2;
    dst[0] = lo; dst[1] = hi;
}

// ---------------------------------------------------------------------------
// Kernel 2: per-row ||n|| -> normalized bf16 N
// ---------------------------------------------------------------------------
__global__ void k_norm_n(const float* __restrict__ n) {
    int b = blockIdx.x, t = threadIdx.x;
    float4 a = reinterpret_cast<const float4*>(n + (size_t)b * D_)[t];
    float nn = a.x*a.x + a.y*a.y + a.z*a.z + a.w*a.w;
    #pragma unroll
    for (int o = 16; o > 0; o >>= 1) nn += __shfl_xor_sync(0xffffffffu, nn, o);
    __shared__ float sn[8];
    __shared__ float s_inv;
    int w = t >> 5, l = t & 31;
    if (l == 0) sn[w] = nn;
    __syncthreads();
    if (t == 0) {
        float NN = 0.f;
        #pragma unroll
        for (int i = 0; i < 8; i++) NN += sn[i];
        float qn = sqrtf(NN);
        s_inv = (qn > 0.f) ? (1.0f / qn) : 0.f;
    }
    __syncthreads();
    float inv = s_inv;
    __nv_bfloat162 lo = __floats2bfloat162_rn(a.x * inv, a.y * inv);
    __nv_bfloat162 hi = __floats2bfloat162_rn(a.z * inv, a.w * inv);
    __nv_bfloat162* dst = reinterpret_cast<__nv_bfloat162*>(g_Nh) + (size_t)b * (D_ / 2) + t * 2;
    dst[0] = lo; dst[1] = hi;
}

// ---------------------------------------------------------------------------
// poly exp on [-1.09, 1.09] (deg-9 Taylor, FMA pipe only)
// ---------------------------------------------------------------------------
__device__ __forceinline__ float poly_exp(float x) {
    float e = 2.7557319e-6f;
    e = fmaf(e, x, 2.4801587e-5f);
    e = fmaf(e, x, 1.9841270e-4f);
    e = fmaf(e, x, 1.3888889e-3f);
    e = fmaf(e, x, 8.3333333e-3f);
    e = fmaf(e, x, 4.1666668e-2f);
    e = fmaf(e, x, 1.6666667e-1f);
    e = fmaf(e, x, 0.5f);
    e = fmaf(e, x, 1.0f);
    e = fmaf(e, x, 1.0f);
    return e;
}

// ---------------------------------------------------------------------------
// cp.async helpers
// ---------------------------------------------------------------------------
__device__ __forceinline__ void cpa16(uint32_t dst_smem, const void* src) {
    asm volatile("cp.async.cg.shared.global [%0], [%1], 16;" :: "r"(dst_smem), "l"(src));
}
__device__ __forceinline__ void cp_commit() { asm volatile("cp.async.commit_group;"); }

// ---------------------------------------------------------------------------
// Kernel 3: wmma GEMM, 128x256 block tile, 64x64 warp tile, BK=64,
// double-buffered cp.async, fused poly-exp + deterministic row partials.
// grid = (NNEG/256, B_/128), block = 256
// ---------------------------------------------------------------------------
__global__ __launch_bounds__(256, 1) void k_gemm() {
    extern __shared__ __align__(16) char smem_raw[];
    __nv_bfloat16* Sb = reinterpret_cast<__nv_bfloat16*>(smem_raw);
    float* Cb = reinterpret_cast<float*>(smem_raw);
    const uint32_t sbase = (uint32_t)__cvta_generic_to_shared(smem_raw);

    const int t = threadIdx.x;
    const int warp = t >> 5;
    const int wm = warp >> 2;     // 0..1 : 64-row strip
    const int wn = warp & 3;      // 0..3 : 64-col strip
    const int bx = blockIdx.x, by = blockIdx.y;

    const __nv_bfloat16* Aptr = g_Qh + (size_t)by * BM * D_;
    const __nv_bfloat16* Bptr = g_Nh + (size_t)bx * BN * D_;

    // loader: A = 1024 16B chunks (4/thread), B = 2048 chunks (8/thread)
    auto load_stage = [&](int s, int k0) {
        uint32_t Abase = sbase + (uint32_t)s * STAGE_ELEMS * 2;
        uint32_t Bbase = Abase + A_STAGE * 2;
        #pragma unroll
        for (int i = 0; i < 4; i++) {
            int c = t + 256 * i;
            int r = c >> 3, c16 = c & 7;
            cpa16(Abase + (uint32_t)(r * (LDA * 2) + c16 * 16),
                  Aptr + (size_t)r * D_ + k0 + c16 * 8);
        }
        #pragma unroll
        for (int i = 0; i < 8; i++) {
            int c = t + 256 * i;
            int r = c >> 3, c16 = c & 7;
            cpa16(Bbase + (uint32_t)(r * (LDA * 2) + c16 * 16),
                  Bptr + (size_t)r * D_ + k0 + c16 * 8);
        }
    };

    wmma::fragment<wmma::accumulator, 16, 16, 16, float> acc[4][4];
    #pragma unroll
    for (int i = 0; i < 4; i++)
        #pragma unroll
        for (int j = 0; j < 4; j++)
            wmma::fill_fragment(acc[i][j], 0.0f);

    load_stage(0, 0);
    cp_commit();

    for (int it = 0; it < NIT; it++) {
        const int cur = it & 1;
        if (it + 1 < NIT) load_stage(cur ^ 1, (it + 1) * BK);
        cp_commit();
        if (it + 1 < NIT) asm volatile("cp.async.wait_group 1;");
        else              asm volatile("cp.async.wait_group 0;");
        __syncthreads();

        const __nv_bfloat16* Ab = Sb + (size_t)cur * STAGE_ELEMS;
        const __nv_bfloat16* Bb = Ab + A_STAGE;
        #pragma unroll
        for (int kk = 0; kk < BK; kk += 16) {
            wmma::fragment<wmma::matrix_a, 16, 16, 16, __nv_bfloat16, wmma::row_major> af[4];
            wmma::fragment<wmma::matrix_b, 16, 16, 16, __nv_bfloat16, wmma::col_major> bfg[4];
            #pragma unroll
            for (int i = 0; i < 4; i++)
                wmma::load_matrix_sync(af[i], Ab + (wm * 64 + 16 * i) * LDA + kk, LDA);
            #pragma unroll
            for (int j = 0; j < 4; j++)
                wmma::load_matrix_sync(bfg[j], Bb + (wn * 64 + 16 * j) * LDA + kk, LDA);
            #pragma unroll
            for (int i = 0; i < 4; i++)
                #pragma unroll
                for (int j = 0; j < 4; j++)
                    wmma::mma_sync(acc[i][j], af[i], bfg[j], acc[i][j]);
        }
        __syncthreads();
    }

    // Epilogue: dump accumulators to smem (pipeline buffers are dead)
    #pragma unroll
    for (int i = 0; i < 4; i++)
        #pragma unroll
        for (int j = 0; j < 4; j++)
            wmma::store_matrix_sync(&Cb[(size_t)(wm * 64 + 16 * i) * EPI_LD + wn * 64 + 16 * j],
                                    acc[i][j], EPI_LD, wmma::mem_row_major);
    __syncthreads();

    // exp + row partial sums: 2 threads per row, 128 cols each
    const int row = t >> 1, half = t & 1;
    const float* cr = &Cb[(size_t)row * EPI_LD + half * 128];
    float s = 0.f;
    #pragma unroll
    for (int j = 0; j < 128; j++)
        s += poly_exp(cr[j] * c_invT);
    s += __shfl_xor_sync(0xffffffffu, s, 1);
    if (half == 0)
        g_part[(size_t)(by * BM + row) * NTILES + bx] = s;  // deterministic
}

// ---------------------------------------------------------------------------
// Kernel 4a: per-row loss term (8192 threads)
// ---------------------------------------------------------------------------
__global__ void k_rowloss() {
    int b = blockIdx.x * 256 + threadIdx.x;
    const float4* pr = reinterpret_cast<const float4*>(&g_part[(size_t)b * NTILES]);
    float s2s = 0.f;
    #pragma unroll
    for (int j = 0; j < NTILES / 4; j++) {
        float4 v = pr[j];
        s2s += v.x + v.y + v.z + v.w;
    }
    float s2 = s2s * (1.0f / (float)NNEG);
    float s1 = expf(g_pos[b] * c_invT);
    g_row[b] = log1pf(s2 / s1);
}

// ---------------------------------------------------------------------------
// Kernel 4b: final scalar reduce
// ---------------------------------------------------------------------------
__global__ void k_reduce(float* __restrict__ out) {
    int t = threadIdx.x;
    double acc = 0.0;
    #pragma unroll
    for (int j = 0; j < 32; j++)
        acc += (double)g_row[t + j * 256];
    #pragma unroll
    for (int o = 16; o > 0; o >>= 1) acc += __shfl_xor_sync(0xffffffffu, acc, o);
    __shared__ double sd[8];
    if ((t & 31) == 0) sd[t >> 5] = acc;
    __syncthreads();
    if (t == 0) {
        double tot = 0.0;
        #pragma unroll
        for (int i = 0; i < 8; i++) tot += sd[i];
        out[0] = (float)(tot / (double)B_);
    }
}

// ---------------------------------------------------------------------------
extern "C" void kernel_launch(void* const* d_in, const int* in_sizes, int n_in,
                              void* d_out, int out_size) {
    const float* q = (const float*)d_in[0];
    const float* p = (const float*)d_in[1];
    const float* n = (const float*)d_in[2];
    float* out = (float*)d_out;

    cudaFuncSetAttribute(k_gemm, cudaFuncAttributeMaxDynamicSharedMemorySize, SMEM_BYTES);

    k_norm_qp<<<B_, 256>>>(q, p);
    k_norm_n<<<NNEG, 256>>>(n);
    k_gemm<<<dim3(NNEG / BN, B_ / BM), 256, SMEM_BYTES>>>();
    k_rowloss<<<B_ / 256, 256>>>();
    k_reduce<<<1, 256>>>(out);
}